// round 1
// baseline (speedup 1.0000x reference)
#include <cuda_runtime.h>
#include <cuda_bf16.h>

#define BATCH 128
#define NANCH 8732
#define NCLS  21
#define KTOP  200
#define CONF_T 0.01f
#define NMS_T  0.45f

// ---------------- scratch (device globals; no allocations allowed) ----------
__device__ float4 g_boxes[BATCH * NANCH];                       // ~17.9 MB
__device__ float  g_probs[(size_t)BATCH * 20 * NANCH];          // ~89.4 MB
__device__ float  g_sc[BATCH * 20 * KTOP];                      // kept scores
__device__ float4 g_sb[BATCH * 20 * KTOP];                      // kept boxes

// ---------------- kernel 1: decode + softmax ---------------------------------
__global__ void prep_kernel(const float* __restrict__ loc,
                            const float* __restrict__ conf,
                            const float* __restrict__ dbox) {
    __shared__ float sc[128 * NCLS];
    int b   = blockIdx.y;
    int n0  = blockIdx.x * 128;
    int tid = threadIdx.x;              // 128 threads
    int nrows = NANCH - n0; if (nrows > 128) nrows = 128;

    const float* cp = conf + ((size_t)b * NANCH + n0) * NCLS;
    for (int i = tid; i < nrows * NCLS; i += 128) sc[i] = cp[i];
    __syncthreads();

    if (tid < nrows) {
        int n = n0 + tid;
        const float* x = &sc[tid * NCLS];
        float m = x[0];
#pragma unroll
        for (int c = 1; c < NCLS; c++) m = fmaxf(m, x[c]);
        float e[NCLS];
        float s = 0.f;
#pragma unroll
        for (int c = 0; c < NCLS; c++) { e[c] = expf(x[c] - m); s += e[c]; }

        // decode box
        float4 l = reinterpret_cast<const float4*>(loc)[(size_t)b * NANCH + n];
        float4 d = reinterpret_cast<const float4*>(dbox)[n];
        float cx = d.x + l.x * 0.1f * d.z;
        float cy = d.y + l.y * 0.1f * d.w;
        float w  = d.z * expf(l.z * 0.2f);
        float h  = d.w * expf(l.w * 0.2f);
        float x1 = cx - w * 0.5f;
        float y1 = cy - h * 0.5f;
        float x2 = x1 + w;
        float y2 = y1 + h;
        x1 = fminf(fmaxf(x1, 0.f), 1.f);
        y1 = fminf(fmaxf(y1, 0.f), 1.f);
        x2 = fminf(fmaxf(x2, 0.f), 1.f);
        y2 = fminf(fmaxf(y2, 0.f), 1.f);
        g_boxes[(size_t)b * NANCH + n] = make_float4(x1, y1, x2, y2);

        // class-major probs (skip background class 0); coalesced per-c row
#pragma unroll
        for (int c = 1; c < NCLS; c++)
            g_probs[((size_t)b * 20 + (c - 1)) * NANCH + n] = e[c] / s;
    }
}

// ---------------- kernel 2: per-(batch,class) top-200 + greedy NMS -----------
struct SmemNMS {
    float4 box[KTOP];
    float  area[KTOP];
    float  score[KTOP];
    int    alive[KTOP];
};
struct Smem2 {
    unsigned long long cand[1024];      // 8192 B (8-aligned: first member)
    union {
        unsigned int keys[NANCH + 4];   // 34944 B
        SmemNMS nms;                    // 5600 B
    } u;
    unsigned int hist[1024];            // 4096 B
    unsigned int cnt;
    unsigned int pivot;
    unsigned int path;
    int kk;
    int doSel;
};

__global__ void nms_kernel() {
    __shared__ Smem2 sm;
    int c   = blockIdx.x;               // 0..19 -> class c+1
    int b   = blockIdx.y;
    int tid = threadIdx.x;              // 256 threads
    const float* row = g_probs + ((size_t)b * 20 + c) * NANCH;

    for (int i = tid; i < 1024; i += 256) sm.hist[i] = 0;
    __syncthreads();

    // pass A: threshold, store keys, histogram bits[30:21]
    for (int n = tid; n < NANCH; n += 256) {
        float s = row[n];
        unsigned k = (s > CONF_T) ? __float_as_uint(s) : 0u;
        sm.u.keys[n] = k;
        if (k) atomicAdd(&sm.hist[(k >> 21) & 1023], 1u);
    }
    __syncthreads();

    if (tid == 0) {
        unsigned tot = 0;
        for (int i = 0; i < 1024; i++) tot += sm.hist[i];
        if (tot <= (unsigned)KTOP) { sm.pivot = 1u; sm.doSel = 0; }
        else {
            sm.doSel = 1;
            int kk = KTOP; unsigned cum = 0; int d = 1023;
            for (; d > 0; d--) {
                unsigned h = sm.hist[d];
                if (cum + h >= (unsigned)kk) break;
                cum += h;
            }
            sm.path = (unsigned)d;
            sm.kk   = kk - (int)cum;
        }
    }
    __syncthreads();

    if (sm.doSel) {
        const int prevsh[3] = {21, 13, 5};
        const int shft[3]   = {13, 5, 0};
        const int nbin[3]   = {256, 256, 32};
        for (int r = 0; r < 3; r++) {
            for (int i = tid; i < nbin[r]; i += 256) sm.hist[i] = 0;
            __syncthreads();
            unsigned path = sm.path;
            int ps = prevsh[r], s2 = shft[r];
            unsigned msk = (unsigned)(nbin[r] - 1);
            for (int n = tid; n < NANCH; n += 256) {
                unsigned k = sm.u.keys[n];
                if (k && (k >> ps) == path)
                    atomicAdd(&sm.hist[(k >> s2) & msk], 1u);
            }
            __syncthreads();
            if (tid == 0) {
                int kk = sm.kk; unsigned cum = 0; int d = nbin[r] - 1;
                for (; d > 0; d--) {
                    unsigned h = sm.hist[d];
                    if (cum + h >= (unsigned)kk) break;
                    cum += h;
                }
                sm.path = (sm.path << ((r < 2) ? 8 : 5)) | (unsigned)d;
                sm.kk   = kk - (int)cum;
            }
            __syncthreads();
        }
        if (tid == 0) sm.pivot = sm.path;   // exact 200th-largest key value
    }
    if (tid == 0) sm.cnt = 0;
    __syncthreads();

    // collect candidates (key >= pivot); 64-bit key = (scorebits, ~index)
    unsigned piv = sm.pivot;
    for (int n = tid; n < NANCH; n += 256) {
        unsigned k = sm.u.keys[n];
        if (k >= piv && k) {
            unsigned p = atomicAdd(&sm.cnt, 1u);
            if (p < 1024)
                sm.cand[p] = ((unsigned long long)k << 32) | (unsigned)(~n);
        }
    }
    __syncthreads();
    unsigned mcnt = sm.cnt; if (mcnt > 1024u) mcnt = 1024u;
    for (int i = tid; i < 1024; i += 256)
        if ((unsigned)i >= mcnt) sm.cand[i] = 0ull;
    __syncthreads();

    // bitonic sort 1024 u64 descending (stable jax.top_k order via ~index)
    for (int kk = 2; kk <= 1024; kk <<= 1) {
        for (int j = kk >> 1; j > 0; j >>= 1) {
            for (int i = tid; i < 1024; i += 256) {
                int ixj = i ^ j;
                if (ixj > i) {
                    unsigned long long a = sm.cand[i], bb = sm.cand[ixj];
                    bool desc = ((i & kk) == 0);
                    if (desc ? (a < bb) : (a > bb)) {
                        sm.cand[i]  = bb;
                        sm.cand[ixj] = a;
                    }
                }
            }
            __syncthreads();
        }
    }

    // fill NMS arrays (overlays keys region — keys no longer needed)
    if (tid < KTOP) {
        unsigned long long v = sm.cand[tid];
        if (v) {
            unsigned kbits = (unsigned)(v >> 32);
            unsigned n = ~(unsigned)(v & 0xFFFFFFFFu);
            float4 bx = g_boxes[(size_t)b * NANCH + n];
            sm.u.nms.box[tid]   = bx;
            sm.u.nms.area[tid]  = (bx.z - bx.x) * (bx.w - bx.y);
            sm.u.nms.score[tid] = __uint_as_float(kbits);
            sm.u.nms.alive[tid] = 1;
        } else {
            sm.u.nms.box[tid]   = make_float4(0.f, 0.f, 0.f, 0.f);
            sm.u.nms.area[tid]  = 0.f;
            sm.u.nms.score[tid] = 0.f;
            sm.u.nms.alive[tid] = 0;
        }
    }
    __syncthreads();

    // greedy NMS: alive[i] is final by step i, so final alive == keep
    for (int i = 0; i < KTOP; i++) {
        if (sm.u.nms.alive[i]) {
            if (tid > i && tid < KTOP && sm.u.nms.alive[tid]) {
                float4 bi = sm.u.nms.box[i];
                float4 bj = sm.u.nms.box[tid];
                float xx1 = fmaxf(bj.x, bi.x), yy1 = fmaxf(bj.y, bi.y);
                float xx2 = fminf(bj.z, bi.z), yy2 = fminf(bj.w, bi.w);
                float inter = fmaxf(xx2 - xx1, 0.f) * fmaxf(yy2 - yy1, 0.f);
                float iou = inter / (sm.u.nms.area[tid] + sm.u.nms.area[i] - inter);
                if (!(iou <= NMS_T)) sm.u.nms.alive[tid] = 0;   // NaN -> suppress
            }
        }
        __syncthreads();
    }

    if (tid < KTOP) {
        bool kept = sm.u.nms.alive[tid] != 0;
        int o = (b * 20 + c) * KTOP + tid;
        g_sc[o] = kept ? sm.u.nms.score[tid] : 0.f;
        g_sb[o] = kept ? sm.u.nms.box[tid] : make_float4(0.f, 0.f, 0.f, 0.f);
    }
}

// ---------------- kernel 3: global top-200 + per-class compaction ------------
__global__ void final_kernel(float* __restrict__ out) {
    __shared__ unsigned long long skey[4096];
    int b   = blockIdx.x;
    int tid = threadIdx.x;              // 256 threads

    for (int i = tid; i < 4096; i += 256) {
        unsigned long long v = 0ull;
        if (i < 4000) {
            float s = g_sc[b * 4000 + i];
            if (s > 0.f)
                v = ((unsigned long long)__float_as_uint(s) << 32) | (unsigned)(~i);
        }
        skey[i] = v;
    }
    __syncthreads();

    for (int kk = 2; kk <= 4096; kk <<= 1) {
        for (int j = kk >> 1; j > 0; j >>= 1) {
            for (int i = tid; i < 4096; i += 256) {
                int ixj = i ^ j;
                if (ixj > i) {
                    unsigned long long a = skey[i], bb = skey[ixj];
                    bool desc = ((i & kk) == 0);
                    if (desc ? (a < bb) : (a > bb)) {
                        skey[i]  = bb;
                        skey[ixj] = a;
                    }
                }
            }
            __syncthreads();
        }
    }

    float* o = out + (size_t)b * NCLS * KTOP * 5;
    for (int i = tid; i < NCLS * KTOP * 5; i += 256) o[i] = 0.f;
    __syncthreads();

    if (tid < 20) {
        int cnt = 0;
        for (int k = 0; k < KTOP; k++) {            // only the global top-200
            unsigned long long v = skey[k];
            if (!v) break;                           // zeros sort last
            unsigned idx = ~(unsigned)(v & 0xFFFFFFFFu);
            if ((int)(idx / KTOP) == tid) {          // class tid+1
                float s = __uint_as_float((unsigned)(v >> 32));
                float4 bx = g_sb[b * 4000 + idx];
                float* dst = o + ((size_t)(tid + 1) * KTOP + cnt) * 5;
                dst[0] = s;
                dst[1] = bx.x; dst[2] = bx.y; dst[3] = bx.z; dst[4] = bx.w;
                cnt++;
            }
        }
    }
}

// ---------------- launch ------------------------------------------------------
extern "C" void kernel_launch(void* const* d_in, const int* in_sizes, int n_in,
                              void* d_out, int out_size) {
    const float* loc  = (const float*)d_in[0];   // [128, 8732, 4]
    const float* conf = (const float*)d_in[1];   // [128, 8732, 21]
    const float* dbox = (const float*)d_in[2];   // [8732, 4]
    float* out = (float*)d_out;                  // [128, 21, 200, 5]

    dim3 g1((NANCH + 127) / 128, BATCH);
    prep_kernel<<<g1, 128>>>(loc, conf, dbox);

    dim3 g2(20, BATCH);
    nms_kernel<<<g2, 256>>>();

    final_kernel<<<BATCH, 256>>>(out);
}

// round 2
// speedup vs baseline: 2.3582x; 2.3582x over previous
#include <cuda_runtime.h>
#include <cuda_bf16.h>

#define BATCH 128
#define NANCH 8732
#define NCLS  21
#define KTOP  200
#define CONF_T 0.01f
#define NMS_T  0.45f

// ---------------- scratch (device globals; no allocations allowed) ----------
__device__ float4 g_boxes[BATCH * NANCH];                       // ~17.9 MB
__device__ float  g_probs[(size_t)BATCH * 20 * NANCH];          // ~89.4 MB
__device__ float  g_sc[BATCH * 20 * KTOP];                      // kept scores
__device__ float4 g_sb[BATCH * 20 * KTOP];                      // kept boxes

// ---------------- kernel 1: decode + softmax ---------------------------------
__global__ void prep_kernel(const float* __restrict__ loc,
                            const float* __restrict__ conf,
                            const float* __restrict__ dbox) {
    __shared__ float sc[128 * NCLS];
    int b   = blockIdx.y;
    int n0  = blockIdx.x * 128;
    int tid = threadIdx.x;              // 128 threads
    int nrows = NANCH - n0; if (nrows > 128) nrows = 128;

    const float* cp = conf + ((size_t)b * NANCH + n0) * NCLS;
    for (int i = tid; i < nrows * NCLS; i += 128) sc[i] = cp[i];
    __syncthreads();

    if (tid < nrows) {
        int n = n0 + tid;
        const float* x = &sc[tid * NCLS];
        float m = x[0];
#pragma unroll
        for (int c = 1; c < NCLS; c++) m = fmaxf(m, x[c]);
        float e[NCLS];
        float s = 0.f;
#pragma unroll
        for (int c = 0; c < NCLS; c++) { e[c] = expf(x[c] - m); s += e[c]; }
        float inv = 1.0f / s;

        // decode box
        float4 l = reinterpret_cast<const float4*>(loc)[(size_t)b * NANCH + n];
        float4 d = reinterpret_cast<const float4*>(dbox)[n];
        float cx = d.x + l.x * 0.1f * d.z;
        float cy = d.y + l.y * 0.1f * d.w;
        float w  = d.z * expf(l.z * 0.2f);
        float h  = d.w * expf(l.w * 0.2f);
        float x1 = cx - w * 0.5f;
        float y1 = cy - h * 0.5f;
        float x2 = x1 + w;
        float y2 = y1 + h;
        x1 = fminf(fmaxf(x1, 0.f), 1.f);
        y1 = fminf(fmaxf(y1, 0.f), 1.f);
        x2 = fminf(fmaxf(x2, 0.f), 1.f);
        y2 = fminf(fmaxf(y2, 0.f), 1.f);
        g_boxes[(size_t)b * NANCH + n] = make_float4(x1, y1, x2, y2);

        // class-major probs (skip background class 0); coalesced per-c row.
        // NOTE: e[c]/s kept as e[c]*inv would change bits; keep exact division
        // semantics identical to round-1 (which passed at 4e-8): use division.
        (void)inv;
#pragma unroll
        for (int c = 1; c < NCLS; c++)
            g_probs[((size_t)b * 20 + (c - 1)) * NANCH + n] = e[c] / s;
    }
}

// ---------------- shared helpers ---------------------------------------------
__device__ __forceinline__ unsigned warp_suffix_incl(unsigned x) {
    unsigned lane = threadIdx.x & 31;
#pragma unroll
    for (int d = 1; d < 32; d <<= 1) {
        unsigned t = __shfl_down_sync(0xffffffffu, x, d);
        if (lane + d < 32) x += t;
    }
    return x;   // sum of x over lanes [lane..31]
}

// exclusive suffix over 256 threads: returns sum of x over threads with tid' > tid
__device__ __forceinline__ unsigned block_excl_suffix_256(unsigned x, unsigned* s_warp) {
    int lane = threadIdx.x & 31, wid = threadIdx.x >> 5;
    unsigned inc = warp_suffix_incl(x);
    if (lane == 0) s_warp[wid] = inc;
    __syncthreads();
    unsigned above = 0;
#pragma unroll
    for (int w = 0; w < 8; w++) if (w > wid) above += s_warp[w];
    return (inc - x) + above;
}

// bitonic sort of 256 u64 keys, descending; one element per thread (blockDim=256).
// sub-warp stages use shfl; cross-warp stages use the provided 256-slot scratch.
__device__ __forceinline__ unsigned long long bitonic256_desc(
        unsigned long long v, unsigned long long* sh) {
    int tid = threadIdx.x;
#pragma unroll
    for (int kk = 2; kk <= 256; kk <<= 1) {
        for (int j = kk >> 1; j > 0; j >>= 1) {
            unsigned long long w;
            if (j >= 32) {
                __syncthreads();
                sh[tid] = v;
                __syncthreads();
                w = sh[tid ^ j];
            } else {
                w = __shfl_xor_sync(0xffffffffu, v, j);
            }
            bool keepMax = ((tid & j) == 0) == ((tid & kk) == 0);
            if (keepMax ? (w > v) : (w < v)) v = w;
        }
    }
    return v;
}

// ---------------- kernel 2: per-(batch,class) top-200 + greedy NMS -----------
// All valid scores s satisfy 0.01 < s <= 1  =>  float bits have bit31=0 and
// bits[30:26] = 01111 (biased exponent in [120,127]). Only bits[25:0] vary, so
// exact 200th-largest selection needs 3 radix rounds: 10 + 8 + 8 bits.
__global__ __launch_bounds__(256) void nms_kernel() {
    __shared__ unsigned hist[1024];
    __shared__ unsigned long long cand[256];
    __shared__ float4 sbox[KTOP];
    __shared__ float  sarea[KTOP];
    __shared__ unsigned char salive[KTOP];
    __shared__ unsigned s_warp[8];
    __shared__ int selBin, selKk;
    __shared__ unsigned s_total, s_cnt;

    int c   = blockIdx.x;               // 0..19 -> class c+1
    int b   = blockIdx.y;
    int tid = threadIdx.x;              // 256 threads
    const float* __restrict__ row = g_probs + ((size_t)b * 20 + c) * NANCH;

    for (int i = tid; i < 1024; i += 256) hist[i] = 0;
    __syncthreads();

    // round 0: histogram bits[25:16] (row stays L2-resident for later passes)
    for (int n = tid; n < NANCH; n += 256) {
        float s = row[n];
        if (s > CONF_T) atomicAdd(&hist[(__float_as_uint(s) >> 16) & 1023u], 1u);
    }
    __syncthreads();

    {   // parallel suffix selection over 1024 bins (4 bins/thread)
        unsigned h0 = hist[4*tid], h1 = hist[4*tid+1], h2 = hist[4*tid+2], h3 = hist[4*tid+3];
        unsigned s3 = h3, s2 = h2 + s3, s1 = h1 + s2, s0 = h0 + s1;
        unsigned E = block_excl_suffix_256(s0, s_warp);
        if (tid == 0) s_total = s0 + E;
        unsigned f0 = s0+E, f1 = s1+E, f2 = s2+E, f3 = s3+E, f4 = E;
        if (f0 >= KTOP && f1 < KTOP) { selBin = 4*tid+0; selKk = KTOP - (int)f1; }
        if (f1 >= KTOP && f2 < KTOP) { selBin = 4*tid+1; selKk = KTOP - (int)f2; }
        if (f2 >= KTOP && f3 < KTOP) { selBin = 4*tid+2; selKk = KTOP - (int)f3; }
        if (f3 >= KTOP && f4 < KTOP) { selBin = 4*tid+3; selKk = KTOP - (int)f4; }
    }
    __syncthreads();

    unsigned pivot = 1u;                 // total<=200 -> take every key
    if (s_total > KTOP) {                // uniform branch
        int d0 = selBin, kk1 = selKk;
        hist[tid] = 0;
        __syncthreads();
        // round 1: bits[15:8] within prefix d0
        for (int n = tid; n < NANCH; n += 256) {
            float s = row[n];
            if (s > CONF_T) {
                unsigned k = __float_as_uint(s);
                if (((k >> 16) & 1023u) == (unsigned)d0)
                    atomicAdd(&hist[(k >> 8) & 255u], 1u);
            }
        }
        __syncthreads();
        {
            unsigned h = hist[tid];
            unsigned E = block_excl_suffix_256(h, s_warp);
            if (h + E >= (unsigned)kk1 && E < (unsigned)kk1) { selBin = tid; selKk = kk1 - (int)E; }
        }
        __syncthreads();
        int d1 = selBin, kk2 = selKk;
        unsigned pref = ((unsigned)d0 << 8) | (unsigned)d1;   // bits[25:8]
        hist[tid] = 0;
        __syncthreads();
        // round 2: bits[7:0] within prefix (d0,d1)
        for (int n = tid; n < NANCH; n += 256) {
            float s = row[n];
            if (s > CONF_T) {
                unsigned k = __float_as_uint(s);
                if (((k >> 8) & 0x3FFFFu) == pref)
                    atomicAdd(&hist[k & 255u], 1u);
            }
        }
        __syncthreads();
        {
            unsigned h = hist[tid];
            unsigned E = block_excl_suffix_256(h, s_warp);
            if (h + E >= (unsigned)kk2 && E < (unsigned)kk2) { selBin = tid; }
        }
        __syncthreads();
        // exact key of the 200th largest score
        pivot = (15u << 26) | ((unsigned)d0 << 16) | ((unsigned)d1 << 8) | (unsigned)selBin;
    }

    if (tid == 0) s_cnt = 0;
    __syncthreads();

    // collect candidates (>= pivot); 64-bit key = (scorebits, ~index) for
    // stable descending order identical to jax.lax.top_k
    for (int n = tid; n < NANCH; n += 256) {
        float s = row[n];
        if (s > CONF_T) {
            unsigned k = __float_as_uint(s);
            if (k >= pivot) {
                unsigned p = atomicAdd(&s_cnt, 1u);
                if (p < 256u) cand[p] = ((unsigned long long)k << 32) | (unsigned)(~n);
            }
        }
    }
    __syncthreads();
    unsigned mcnt = s_cnt < 256u ? s_cnt : 256u;
    unsigned long long v = (tid < (int)mcnt) ? cand[tid] : 0ull;
    v = bitonic256_desc(v, cand);
    __syncthreads();              // all scratch reads done before overwrite
    cand[tid] = v;
    __syncthreads();

    // NMS state: own candidate in registers, broadcast state in shared
    bool   myAlive = false;
    float4 myBox   = make_float4(0.f, 0.f, 0.f, 0.f);
    float  myArea  = 0.f;
    if (tid < KTOP) {
        unsigned long long vv = cand[tid];
        if (vv) {
            unsigned n = ~(unsigned)(vv & 0xFFFFFFFFu);
            myBox  = g_boxes[(size_t)b * NANCH + n];
            myArea = (myBox.z - myBox.x) * (myBox.w - myBox.y);
            myAlive = true;
        }
        sbox[tid]   = myBox;
        sarea[tid]  = myArea;
        salive[tid] = myAlive ? 1 : 0;
    }
    __syncthreads();

    // greedy NMS: alive[i] is final by step i, so final alive == keep
    for (int i = 0; i < KTOP; i++) {
        if (salive[i]) {                          // uniform read
            if (tid > i && myAlive) {
                float4 bi = sbox[i];
                float xx1 = fmaxf(myBox.x, bi.x), yy1 = fmaxf(myBox.y, bi.y);
                float xx2 = fminf(myBox.z, bi.z), yy2 = fminf(myBox.w, bi.w);
                float inter = fmaxf(xx2 - xx1, 0.f) * fmaxf(yy2 - yy1, 0.f);
                float iou = inter / (myArea + sarea[i] - inter);
                if (!(iou <= NMS_T)) { myAlive = false; salive[tid] = 0; }  // NaN -> suppress
            }
        }
        __syncthreads();
    }

    if (tid < KTOP) {
        int o = (b * 20 + c) * KTOP + tid;
        g_sc[o] = myAlive ? __uint_as_float((unsigned)(cand[tid] >> 32)) : 0.f;
        g_sb[o] = myAlive ? myBox : make_float4(0.f, 0.f, 0.f, 0.f);
    }
}

// ---------------- kernel 3: global top-200 + per-class compaction ------------
__global__ __launch_bounds__(256) void final_kernel(float* __restrict__ out) {
    __shared__ unsigned hist[1024];
    __shared__ unsigned long long cand[256];
    __shared__ unsigned s_warp[8];
    __shared__ int selBin, selKk;
    __shared__ unsigned s_total, s_cnt;

    int b   = blockIdx.x;
    int tid = threadIdx.x;              // 256 threads
    const float* __restrict__ sc = g_sc + b * 4000;

    for (int i = tid; i < 1024; i += 256) hist[i] = 0;
    __syncthreads();
    for (int n = tid; n < 4000; n += 256) {
        float s = sc[n];                // kept scores are 0 or > 0.01
        if (s > 0.f) atomicAdd(&hist[(__float_as_uint(s) >> 16) & 1023u], 1u);
    }
    __syncthreads();
    {
        unsigned h0 = hist[4*tid], h1 = hist[4*tid+1], h2 = hist[4*tid+2], h3 = hist[4*tid+3];
        unsigned s3 = h3, s2 = h2 + s3, s1 = h1 + s2, s0 = h0 + s1;
        unsigned E = block_excl_suffix_256(s0, s_warp);
        if (tid == 0) s_total = s0 + E;
        unsigned f0 = s0+E, f1 = s1+E, f2 = s2+E, f3 = s3+E, f4 = E;
        if (f0 >= KTOP && f1 < KTOP) { selBin = 4*tid+0; selKk = KTOP - (int)f1; }
        if (f1 >= KTOP && f2 < KTOP) { selBin = 4*tid+1; selKk = KTOP - (int)f2; }
        if (f2 >= KTOP && f3 < KTOP) { selBin = 4*tid+2; selKk = KTOP - (int)f3; }
        if (f3 >= KTOP && f4 < KTOP) { selBin = 4*tid+3; selKk = KTOP - (int)f4; }
    }
    __syncthreads();

    unsigned pivot = 1u;
    if (s_total > KTOP) {
        int d0 = selBin, kk1 = selKk;
        hist[tid] = 0;
        __syncthreads();
        for (int n = tid; n < 4000; n += 256) {
            float s = sc[n];
            if (s > 0.f) {
                unsigned k = __float_as_uint(s);
                if (((k >> 16) & 1023u) == (unsigned)d0)
                    atomicAdd(&hist[(k >> 8) & 255u], 1u);
            }
        }
        __syncthreads();
        {
            unsigned h = hist[tid];
            unsigned E = block_excl_suffix_256(h, s_warp);
            if (h + E >= (unsigned)kk1 && E < (unsigned)kk1) { selBin = tid; selKk = kk1 - (int)E; }
        }
        __syncthreads();
        int d1 = selBin, kk2 = selKk;
        unsigned pref = ((unsigned)d0 << 8) | (unsigned)d1;
        hist[tid] = 0;
        __syncthreads();
        for (int n = tid; n < 4000; n += 256) {
            float s = sc[n];
            if (s > 0.f) {
                unsigned k = __float_as_uint(s);
                if (((k >> 8) & 0x3FFFFu) == pref)
                    atomicAdd(&hist[k & 255u], 1u);
            }
        }
        __syncthreads();
        {
            unsigned h = hist[tid];
            unsigned E = block_excl_suffix_256(h, s_warp);
            if (h + E >= (unsigned)kk2 && E < (unsigned)kk2) { selBin = tid; }
        }
        __syncthreads();
        pivot = (15u << 26) | ((unsigned)d0 << 16) | ((unsigned)d1 << 8) | (unsigned)selBin;
    }

    if (tid == 0) s_cnt = 0;
    __syncthreads();
    for (int n = tid; n < 4000; n += 256) {
        float s = sc[n];
        if (s > 0.f) {
            unsigned k = __float_as_uint(s);
            if (k >= pivot) {
                unsigned p = atomicAdd(&s_cnt, 1u);
                if (p < 256u) cand[p] = ((unsigned long long)k << 32) | (unsigned)(~n);
            }
        }
    }
    __syncthreads();
    unsigned mcnt = s_cnt < 256u ? s_cnt : 256u;
    unsigned long long v = (tid < (int)mcnt) ? cand[tid] : 0ull;
    v = bitonic256_desc(v, cand);
    __syncthreads();
    cand[tid] = v;
    __syncthreads();

    // zero the whole batch output (poisoned by harness), then compact
    float* o = out + (size_t)b * NCLS * KTOP * 5;
    for (int i = tid; i < NCLS * KTOP * 5; i += 256) o[i] = 0.f;
    __syncthreads();

    if (tid < 20) {
        int cnt = 0;
        for (int k = 0; k < KTOP; k++) {            // global top-200 only
            unsigned long long vv = cand[k];
            if (!vv) break;                          // zeros sort last
            unsigned idx = ~(unsigned)(vv & 0xFFFFFFFFu);
            if ((int)(idx / KTOP) == tid) {          // class tid+1
                float s = __uint_as_float((unsigned)(vv >> 32));
                float4 bx = g_sb[b * 4000 + idx];
                float* dst = o + ((size_t)(tid + 1) * KTOP + cnt) * 5;
                dst[0] = s;
                dst[1] = bx.x; dst[2] = bx.y; dst[3] = bx.z; dst[4] = bx.w;
                cnt++;
            }
        }
    }
}

// ---------------- launch ------------------------------------------------------
extern "C" void kernel_launch(void* const* d_in, const int* in_sizes, int n_in,
                              void* d_out, int out_size) {
    const float* loc  = (const float*)d_in[0];   // [128, 8732, 4]
    const float* conf = (const float*)d_in[1];   // [128, 8732, 21]
    const float* dbox = (const float*)d_in[2];   // [8732, 4]
    float* out = (float*)d_out;                  // [128, 21, 200, 5]

    dim3 g1((NANCH + 127) / 128, BATCH);
    prep_kernel<<<g1, 128>>>(loc, conf, dbox);

    dim3 g2(20, BATCH);
    nms_kernel<<<g2, 256>>>();

    final_kernel<<<BATCH, 256>>>(out);
}